// round 3
// baseline (speedup 1.0000x reference)
#include <cuda_runtime.h>
#include <cuda_fp16.h>
#include <cstdint>

#define DINL __device__ __forceinline__

constexpr int NROWS   = 65536;
constexpr int DFEAT   = 32;
constexpr int H       = 128;
constexpr int SPLITS  = 32;
constexpr int ROWS_PER_BLOCK = NROWS / SPLITS;   // 2048
constexpr int TILES   = ROWS_PER_BLOCK / 128;    // 16
constexpr int NTHREADS = 256;

// dynamic SMEM layout (bytes)
constexpr int SM_W1   = 0;      // 128 floats
constexpr int SM_B1   = 512;
constexpr int SM_B2   = 1024;
constexpr int SM_W3   = 1536;
constexpr int SM_PART = 2048;   // partial[2][4][128] floats = 4096 B
constexpr int SM_A0   = 8192;   // A tile buf0: 128 rows x 256 B (swizzled) = 32 KB
constexpr int SM_A1   = SM_A0 + 32768;
constexpr int SM_TOTAL = SM_A1 + 32768;          // 73728 B

DINL uint32_t smem_u32(const void* p) {
    uint32_t a;
    asm("{ .reg .u64 t; cvta.to.shared.u64 t, %1; cvt.u32.u64 %0, t; }"
        : "=r"(a) : "l"(p));
    return a;
}

DINL void ldsm_x4(uint32_t& a0, uint32_t& a1, uint32_t& a2, uint32_t& a3,
                  uint32_t addr) {
    asm volatile("ldmatrix.sync.aligned.m8n8.x4.shared.b16 {%0,%1,%2,%3}, [%4];"
                 : "=r"(a0), "=r"(a1), "=r"(a2), "=r"(a3) : "r"(addr));
}

DINL void mma16816(float* c, uint32_t a0, uint32_t a1, uint32_t a2, uint32_t a3,
                   uint32_t b0, uint32_t b1) {
    asm volatile(
        "mma.sync.aligned.m16n8k16.row.col.f32.f16.f16.f32 "
        "{%0,%1,%2,%3}, {%4,%5,%6,%7}, {%8,%9}, {%0,%1,%2,%3};"
        : "+f"(c[0]), "+f"(c[1]), "+f"(c[2]), "+f"(c[3])
        : "r"(a0), "r"(a1), "r"(a2), "r"(a3), "r"(b0), "r"(b1));
}

__global__ void __launch_bounds__(NTHREADS, 1)
kan_kernel(const float* __restrict__ x,  const float* __restrict__ W1,
           const float* __restrict__ b1, const float* __restrict__ W2,
           const float* __restrict__ b2, const float* __restrict__ W3,
           const float* __restrict__ b3, float* __restrict__ out)
{
    extern __shared__ char smem[];
    const uint32_t sb = smem_u32(smem);

    float* w1s = reinterpret_cast<float*>(smem + SM_W1);
    float* b1s = reinterpret_cast<float*>(smem + SM_B1);
    float* b2s = reinterpret_cast<float*>(smem + SM_B2);
    float* w3s = reinterpret_cast<float*>(smem + SM_W3);
    float* part = reinterpret_cast<float*>(smem + SM_PART); // [2][4][128]

    const int tid  = threadIdx.x;
    const int d    = blockIdx.x & (DFEAT - 1);   // feature fastest -> x L2 reuse
    const int split = blockIdx.x >> 5;
    const int n0   = split * ROWS_PER_BLOCK;

    const int lane = tid & 31, warp = tid >> 5;
    const int wm = warp & 1;        // 2 row-groups of 64
    const int wn = warp >> 1;       // 4 col-groups of 32
    const int tig = lane & 3, gid = lane >> 2;

    // ---- preload small weights into SMEM ----
    for (int i = tid; i < H; i += NTHREADS) {
        w1s[i] = W1[d * H + i];
        b1s[i] = b1[d * H + i];
        b2s[i] = b2[d * H + i];
        w3s[i] = W3[d * H + i];
    }
    const float b3d = b3[d];

    // ---- load B (W2) fragments into registers, once per block ----
    // mma m16n8k16 .col B frag: lane holds (k,n): n = gid, k = 2*tig(+1), +8(+9)
    uint32_t bfrag[8][4][2];
    {
        const float* w2d = W2 + (size_t)d * H * H;
        #pragma unroll
        for (int ks = 0; ks < 8; ++ks) {
            #pragma unroll
            for (int nf = 0; nf < 4; ++nf) {
                const int n  = wn * 32 + nf * 8 + gid;
                const int ka = ks * 16 + tig * 2;
                float f0 = w2d[(ka    ) * H + n];
                float f1 = w2d[(ka + 1) * H + n];
                float f2 = w2d[(ka + 8) * H + n];
                float f3 = w2d[(ka + 9) * H + n];
                __half2 h0 = __floats2half2_rn(f0, f1);
                __half2 h1v = __floats2half2_rn(f2, f3);
                bfrag[ks][nf][0] = *reinterpret_cast<uint32_t*>(&h0);
                bfrag[ks][nf][1] = *reinterpret_cast<uint32_t*>(&h1v);
            }
        }
    }

    // CRITICAL: weights in SMEM must be visible to ALL threads before produce()
    __syncthreads();

    const int prow  = tid >> 1;      // producer row (2 threads/row)
    const int phalf = tid & 1;

    // ---- h1 producer: writes one 128x128 fp16 tile into swizzled SMEM ----
    // SMEM A layout: row-major 256B rows, 16B granules XOR-swizzled by (row&15)
    auto produce = [&](float xv, int buf) {
        char* A = smem + (buf ? SM_A1 : SM_A0);
        #pragma unroll
        for (int j = 0; j < 8; ++j) {
            const int g  = phalf * 8 + j;      // granule index 0..15
            const int c0 = g * 8;              // first col of granule
            float v0 = fmaxf(fmaf(xv, w1s[c0 + 0], b1s[c0 + 0]), 0.f);
            float v1 = fmaxf(fmaf(xv, w1s[c0 + 1], b1s[c0 + 1]), 0.f);
            float v2 = fmaxf(fmaf(xv, w1s[c0 + 2], b1s[c0 + 2]), 0.f);
            float v3 = fmaxf(fmaf(xv, w1s[c0 + 3], b1s[c0 + 3]), 0.f);
            float v4 = fmaxf(fmaf(xv, w1s[c0 + 4], b1s[c0 + 4]), 0.f);
            float v5 = fmaxf(fmaf(xv, w1s[c0 + 5], b1s[c0 + 5]), 0.f);
            float v6 = fmaxf(fmaf(xv, w1s[c0 + 6], b1s[c0 + 6]), 0.f);
            float v7 = fmaxf(fmaf(xv, w1s[c0 + 7], b1s[c0 + 7]), 0.f);
            __half2 p0 = __floats2half2_rn(v0, v1);
            __half2 p1 = __floats2half2_rn(v2, v3);
            __half2 p2 = __floats2half2_rn(v4, v5);
            __half2 p3 = __floats2half2_rn(v6, v7);
            uint4 u;
            u.x = *reinterpret_cast<uint32_t*>(&p0);
            u.y = *reinterpret_cast<uint32_t*>(&p1);
            u.z = *reinterpret_cast<uint32_t*>(&p2);
            u.w = *reinterpret_cast<uint32_t*>(&p3);
            const uint32_t byte = (uint32_t)prow * 256u
                                + (uint32_t)((g ^ (prow & 15)) << 4);
            *reinterpret_cast<uint4*>(A + byte) = u;
        }
    };

    // produce tile 0
    {
        const float xv0 = x[(size_t)(n0 + prow) * DFEAT + d];
        produce(xv0, 0);
    }
    __syncthreads();

    // epilogue constants per lane: col(nf,eb) = wn*32 + nf*8 + tig*2 + eb
    float b2r[4][2], w3r[4][2];
    #pragma unroll
    for (int nf = 0; nf < 4; ++nf) {
        #pragma unroll
        for (int eb = 0; eb < 2; ++eb) {
            const int col = wn * 32 + nf * 8 + tig * 2 + eb;
            b2r[nf][eb] = b2s[col];
            w3r[nf][eb] = w3s[col];
        }
    }

    // ldmatrix lane-address components (within 128-row tile)
    const int g2 = lane >> 3;          // 0..3 matrix index
    const int ri = lane & 7;
    const int row_local = (g2 & 1) * 8 + ri;           // rows within 16-row frag
    const int gran_hi   = g2 >> 1;                      // k-granule select

    for (int t = 0; t < TILES; ++t) {
        const int buf = t & 1;
        const uint32_t Abase = sb + (buf ? SM_A1 : SM_A0);

        // prefetch next tile's x (hidden under the MMA phase)
        float xnext = 0.f;
        if (t + 1 < TILES)
            xnext = x[(size_t)(n0 + (t + 1) * 128 + prow) * DFEAT + d];

        // ---- MMA consume: 128x128x128, warp tile 64x32 ----
        float acc[4][4][4];
        #pragma unroll
        for (int mf = 0; mf < 4; ++mf)
            #pragma unroll
            for (int nf = 0; nf < 4; ++nf)
                #pragma unroll
                for (int e = 0; e < 4; ++e) acc[mf][nf][e] = 0.f;

        #pragma unroll
        for (int ks = 0; ks < 8; ++ks) {
            #pragma unroll
            for (int mf = 0; mf < 4; ++mf) {
                const int rowfull = wm * 64 + mf * 16 + row_local;
                const int gran    = ks * 2 + gran_hi;
                const uint32_t addr = Abase + (uint32_t)rowfull * 256u
                                    + (uint32_t)((gran ^ (rowfull & 15)) << 4);
                uint32_t a0, a1, a2, a3;
                ldsm_x4(a0, a1, a2, a3, addr);
                #pragma unroll
                for (int nf = 0; nf < 4; ++nf)
                    mma16816(acc[mf][nf], a0, a1, a2, a3,
                             bfrag[ks][nf][0], bfrag[ks][nf][1]);
            }
        }

        // ---- epilogue: relu(acc + b2) * W3, row-reduce ----
        #pragma unroll
        for (int mf = 0; mf < 4; ++mf) {
            float r0 = 0.f, r1 = 0.f;
            #pragma unroll
            for (int nf = 0; nf < 4; ++nf) {
                #pragma unroll
                for (int eb = 0; eb < 2; ++eb) {
                    r0 += fmaxf(acc[mf][nf][eb]     + b2r[nf][eb], 0.f) * w3r[nf][eb];
                    r1 += fmaxf(acc[mf][nf][2 + eb] + b2r[nf][eb], 0.f) * w3r[nf][eb];
                }
            }
            r0 += __shfl_xor_sync(0xffffffffu, r0, 1);
            r0 += __shfl_xor_sync(0xffffffffu, r0, 2);
            r1 += __shfl_xor_sync(0xffffffffu, r1, 1);
            r1 += __shfl_xor_sync(0xffffffffu, r1, 2);
            if (tig == 0) {
                const int r = wm * 64 + mf * 16 + gid;
                part[(buf * 4 + wn) * 128 + r    ] = r0;
                part[(buf * 4 + wn) * 128 + r + 8] = r1;
            }
        }

        // ---- overlap: produce next tile into the other buffer ----
        if (t + 1 < TILES) produce(xnext, buf ^ 1);
        __syncthreads();

        // ---- cross-warp reduce + global accumulate ----
        if (tid < 128) {
            float s = part[(buf * 4 + 0) * 128 + tid]
                    + part[(buf * 4 + 1) * 128 + tid]
                    + part[(buf * 4 + 2) * 128 + tid]
                    + part[(buf * 4 + 3) * 128 + tid] + b3d;
            atomicAdd(out + n0 + t * 128 + tid, s);
        }
    }
}

extern "C" void kernel_launch(void* const* d_in, const int* in_sizes, int n_in,
                              void* d_out, int out_size) {
    const float* x  = (const float*)d_in[0];
    const float* W1 = (const float*)d_in[1];
    const float* b1 = (const float*)d_in[2];
    const float* W2 = (const float*)d_in[3];
    const float* b2 = (const float*)d_in[4];
    const float* W3 = (const float*)d_in[5];
    const float* b3 = (const float*)d_in[6];
    float* out = (float*)d_out;

    cudaFuncSetAttribute(kan_kernel, cudaFuncAttributeMaxDynamicSharedMemorySize,
                         SM_TOTAL);
    cudaMemsetAsync(d_out, 0, (size_t)out_size * sizeof(float), 0);
    kan_kernel<<<DFEAT * SPLITS, NTHREADS, SM_TOTAL>>>(x, W1, b1, W2, b2, W3, b3, out);
}